// round 14
// baseline (speedup 1.0000x reference)
#include <cuda_runtime.h>

#define NBATCH 4
#define NPTS   8192
#define NC     16
#define NCELLS (NC * NC * NC)     // 4096
#define PTH    512                // prep threads
#define STH    256                // search threads (2 per query)
#define QPB    (STH / 2)          // 128 queries per block
#define SBLK   (NPTS / QPB)       // 64 search blocks per (dir,b)
#define GROUPS 8

__device__ float        g_box[2][NBATCH][6];        // min xyz, max xyz
__device__ int          g_start[2][NBATCH][NCELLS + 1];
__device__ float4       g_sorted[2][NBATCH][NPTS];  // cell-sorted, w = ||p||^2
__device__ double       g_part[GROUPS][SBLK];
__device__ double       g_gsum[GROUPS];
__device__ unsigned int g_c1[GROUPS];               // zero-init; reset by finisher
__device__ unsigned int g_c2;                       // zero-init; reset by finisher

__device__ __forceinline__ int cidx(float v, float bmin, float inv) {
    int i = (int)((v - bmin) * inv);
    return min(max(i, 0), NC - 1);
}

// ---- one fused prep: bbox -> histogram -> scan -> scatter (per set,batch) ----
__global__ __launch_bounds__(PTH) void k_prep(const float* __restrict__ rec,
                                              const float* __restrict__ data) {
    __shared__ float          sbox[6][PTH];
    __shared__ int            hist[NCELLS];
    __shared__ unsigned short cells[NPTS];
    __shared__ int            ssum[PTH];

    const int s   = blockIdx.x >> 2;
    const int b   = blockIdx.x & 3;
    const int tid = threadIdx.x;
    const float* src = (s == 0 ? rec : data) + (size_t)b * NPTS * 3;

    // phase 1: bounding box
    float mn0 = 3.4e38f, mn1 = 3.4e38f, mn2 = 3.4e38f;
    float mx0 = -3.4e38f, mx1 = -3.4e38f, mx2 = -3.4e38f;
    for (int i = tid; i < NPTS; i += PTH) {
        float x = src[3 * i], y = src[3 * i + 1], z = src[3 * i + 2];
        mn0 = fminf(mn0, x); mx0 = fmaxf(mx0, x);
        mn1 = fminf(mn1, y); mx1 = fmaxf(mx1, y);
        mn2 = fminf(mn2, z); mx2 = fmaxf(mx2, z);
    }
    sbox[0][tid] = mn0; sbox[1][tid] = mn1; sbox[2][tid] = mn2;
    sbox[3][tid] = mx0; sbox[4][tid] = mx1; sbox[5][tid] = mx2;
    __syncthreads();
    for (int st = PTH / 2; st > 0; st >>= 1) {
        if (tid < st) {
            #pragma unroll
            for (int a = 0; a < 3; ++a) {
                sbox[a][tid]     = fminf(sbox[a][tid],     sbox[a][tid + st]);
                sbox[a + 3][tid] = fmaxf(sbox[a + 3][tid], sbox[a + 3][tid + st]);
            }
        }
        __syncthreads();
    }
    if (tid < 6) g_box[s][b][tid] = sbox[tid][0];
    const float bx0 = sbox[0][0], by0 = sbox[1][0], bz0 = sbox[2][0];
    const float ivx = NC / (sbox[3][0] - bx0 + 1e-6f);
    const float ivy = NC / (sbox[4][0] - by0 + 1e-6f);
    const float ivz = NC / (sbox[5][0] - bz0 + 1e-6f);
    __syncthreads();

    // phase 2: histogram (smem)
    for (int i = tid; i < NCELLS; i += PTH) hist[i] = 0;
    __syncthreads();
    for (int i = tid; i < NPTS; i += PTH) {
        float x = src[3 * i], y = src[3 * i + 1], z = src[3 * i + 2];
        int c = (cidx(z, bz0, ivz) * NC + cidx(y, by0, ivy)) * NC + cidx(x, bx0, ivx);
        cells[i] = (unsigned short)c;
        atomicAdd(&hist[c], 1);
    }
    __syncthreads();

    // phase 3: exclusive scan (8 cells/thread + block scan)
    const int base = tid * 8;
    int loc[8], tot = 0;
    #pragma unroll
    for (int j = 0; j < 8; ++j) { loc[j] = tot; tot += hist[base + j]; }
    ssum[tid] = tot;
    __syncthreads();
    for (int off = 1; off < PTH; off <<= 1) {
        int v = (tid >= off) ? ssum[tid - off] : 0;
        __syncthreads();
        ssum[tid] += v;
        __syncthreads();
    }
    const int ex = ssum[tid] - tot;
    #pragma unroll
    for (int j = 0; j < 8; ++j) g_start[s][b][base + j] = ex + loc[j];
    if (tid == PTH - 1) g_start[s][b][NCELLS] = NPTS;
    __syncthreads();
    #pragma unroll
    for (int j = 0; j < 8; ++j) hist[base + j] = ex + loc[j];   // cursors
    __syncthreads();

    // phase 4: scatter (w = norm)
    for (int i = tid; i < NPTS; i += PTH) {
        int c = cells[i];
        int pos = atomicAdd(&hist[c], 1);
        float x = src[3 * i], y = src[3 * i + 1], z = src[3 * i + 2];
        g_sorted[s][b][pos] = make_float4(x, y, z, fmaf(x, x, fmaf(y, y, z * z)));
    }
}

// ---- exact NN: 2 threads/query, role-split rows, pair-shfl combine ----
__global__ __launch_bounds__(STH) void k_search(float* __restrict__ out) {
    const int tid  = threadIdx.x;
    const int role = tid & 1;                    // pair role
    const int lane = tid & 31;
    const unsigned pmask = 0x3u << (lane & ~1);  // this pair's lanes
    const int dir = blockIdx.z;                  // 0: rec->data, 1: data->rec
    const int b   = blockIdx.y;
    const int qi  = blockIdx.x * QPB + (tid >> 1);
    const int ds  = 1 - dir;
    const int group = dir * NBATCH + b;

    const float4 q = g_sorted[dir][b][qi];
    const float* bx = g_box[ds][b];
    const float rx = bx[3] - bx[0] + 1e-6f;
    const float ry = bx[4] - bx[1] + 1e-6f;
    const float rz = bx[5] - bx[2] + 1e-6f;
    const float ivx = NC / rx, ivy = NC / ry, ivz = NC / rz;
    const float hmin = fminf(rx, fminf(ry, rz)) * (1.0f / NC);

    const float A0 = -2.0f * q.x, A1 = -2.0f * q.y, A2 = -2.0f * q.z;
    const float q2 = q.w;
    const int cx = cidx(q.x, bx[0], ivx);
    const int cy = cidx(q.y, bx[1], ivy);
    const int cz = cidx(q.z, bx[2], ivz);

    const float4* __restrict__ pts = g_sorted[ds][b];
    const int*    __restrict__ stt = g_start[ds][b];

    float b0 = 3.4e38f, b1 = 3.4e38f;
    const int xlo1 = max(cx - 1, 0), xhi1 = min(cx + 1, NC - 1);

    // ---- fast path: 9 rows; this thread takes rows with parity == role.
    //      Prefetch its (<=5) run bounds first for MLP. ----
    int rs[5], re[5], nr = 0;
    {
        int row = 0;
        #pragma unroll
        for (int dz = -1; dz <= 1; ++dz) {
            const int z = cz + dz;
            #pragma unroll
            for (int dy = -1; dy <= 1; ++dy, ++row) {
                if ((row & 1) != role) continue;
                const int y = cy + dy;
                if (z < 0 || z >= NC || y < 0 || y >= NC) continue;
                const int rb = (z * NC + y) * NC;
                rs[nr] = stt[rb + xlo1];
                re[nr] = stt[rb + xhi1 + 1];
                ++nr;
            }
        }
    }
    for (int r = 0; r < nr; ++r) {
        int i = rs[r];
        const int e = re[r];
        for (; i + 1 < e; i += 2) {
            float4 p  = pts[i];
            float4 p2 = pts[i + 1];
            b0 = fminf(b0, fmaf(A2, p.z,  fmaf(A1, p.y,  fmaf(A0, p.x,  q2))) + p.w);
            b1 = fminf(b1, fmaf(A2, p2.z, fmaf(A1, p2.y, fmaf(A0, p2.x, q2))) + p2.w);
        }
        if (i < e) {
            float4 p = pts[i];
            b0 = fminf(b0, fmaf(A2, p.z, fmaf(A1, p.y, fmaf(A0, p.x, q2))) + p.w);
        }
    }
    float best = fminf(b0, b1);
    best = fminf(best, __shfl_xor_sync(pmask, best, 1));

    // ---- rare path: incremental Chebyshev shells until bound proves done.
    //      Pair lanes share `best` -> identical control flow; rows split by
    //      parity of the shell row counter. ----
    if (best > hmin * hmin) {
        for (int k = 2; k < NC; ++k) {
            const float lb = (k - 1) * hmin;
            if (best <= lb * lb) break;
            float nb = best;
            int row = 0;
            for (int dz = -k; dz <= k; ++dz) {
                const int z = cz + dz;
                const int adz = (dz < 0) ? -dz : dz;
                for (int dy = -k; dy <= k; ++dy, ++row) {
                    if ((row & 1) != role) continue;
                    const int y = cy + dy;
                    if (z < 0 || z >= NC || y < 0 || y >= NC) continue;
                    const int ady = (dy < 0) ? -dy : dy;
                    const int rb = (z * NC + y) * NC;
                    if (adz == k || ady == k) {
                        // boundary row: full x run (new at this k)
                        const int xl = max(cx - k, 0), xh = min(cx + k, NC - 1);
                        int i = stt[rb + xl];
                        const int e = stt[rb + xh + 1];
                        for (; i < e; ++i) {
                            float4 p = pts[i];
                            nb = fminf(nb,
                                fmaf(A2, p.z, fmaf(A1, p.y, fmaf(A0, p.x, q2))) + p.w);
                        }
                    } else {
                        // interior row: only the two x = cx +- k stubs are new
                        const int xm = cx - k, xp = cx + k;
                        if (xm >= 0) {
                            int i = stt[rb + xm];
                            const int e = stt[rb + xm + 1];
                            for (; i < e; ++i) {
                                float4 p = pts[i];
                                nb = fminf(nb,
                                    fmaf(A2, p.z, fmaf(A1, p.y, fmaf(A0, p.x, q2))) + p.w);
                            }
                        }
                        if (xp < NC) {
                            int i = stt[rb + xp];
                            const int e = stt[rb + xp + 1];
                            for (; i < e; ++i) {
                                float4 p = pts[i];
                                nb = fminf(nb,
                                    fmaf(A2, p.z, fmaf(A1, p.y, fmaf(A0, p.x, q2))) + p.w);
                            }
                        }
                    }
                }
            }
            nb = fminf(nb, __shfl_xor_sync(pmask, nb, 1));
            best = nb;
        }
    }

    // ---- double-precision reduction (scatter-order independent) ----
    __shared__ double red[STH];
    __shared__ int    s_flag;
    red[tid] = (role == 0) ? (double)fmaxf(best, 0.0f) : 0.0;
    __syncthreads();
    for (int st = STH / 2; st > 0; st >>= 1) {
        if (tid < st) red[tid] += red[tid + st];
        __syncthreads();
    }
    if (tid == 0) {
        g_part[group][blockIdx.x] = red[0];
        __threadfence();
        unsigned int t = atomicAdd(&g_c1[group], 1u);
        s_flag = (t == SBLK - 1) ? 1 : 0;
    }
    __syncthreads();

    if (s_flag && tid == 0) {
        __threadfence();
        double ssum = 0.0;
        #pragma unroll
        for (int c = 0; c < SBLK; ++c) ssum += g_part[group][c];
        g_gsum[group] = ssum;
        __threadfence();
        unsigned int t2 = atomicAdd(&g_c2, 1u);
        if (t2 == GROUPS - 1) {
            __threadfence();
            double total = 0.0;
            #pragma unroll
            for (int bb = 0; bb < NBATCH; ++bb) {
                double mr = g_gsum[0 * NBATCH + bb] * (1.0 / NPTS);
                double md = g_gsum[1 * NBATCH + bb] * (1.0 / NPTS);
                total += (mr > md) ? mr : md;
            }
            out[0] = (float)(total * (1.0 / NBATCH));
            #pragma unroll
            for (int gg = 0; gg < GROUPS; ++gg) g_c1[gg] = 0u;
            g_c2 = 0u;
        }
    }
}

extern "C" void kernel_launch(void* const* d_in, const int* in_sizes, int n_in,
                              void* d_out, int out_size) {
    const float* rec  = (const float*)d_in[0];   // (B, N, 3) fp32
    const float* data = (const float*)d_in[1];   // (B, M, 3) fp32
    float* out = (float*)d_out;

    k_prep<<<8, PTH>>>(rec, data);
    dim3 sgrid(SBLK, NBATCH, 2);                 // 64 x 4 x 2 = 512 blocks
    k_search<<<sgrid, STH>>>(out);
}

// round 15
// speedup vs baseline: 1.1953x; 1.1953x over previous
#include <cuda_runtime.h>

#define NBATCH 4
#define NPTS   8192
#define NC     16
#define NCELLS (NC * NC * NC)     // 4096
#define PTH    512                // prep threads
#define STH    128                // search threads (1 query each)
#define SBLK   (NPTS / STH)       // 64 search blocks per (dir,b)
#define GROUPS 8
#define ZSPAN  6                  // max staged z-planes
#define CAP    2048               // max staged points (32 KB)

__device__ float        g_box[2][NBATCH][6];        // min xyz, max xyz
__device__ int          g_start[2][NBATCH][NCELLS + 1];
__device__ float4       g_sorted[2][NBATCH][NPTS];  // cell-sorted, w = ||p||^2
__device__ double       g_part[GROUPS][SBLK];
__device__ double       g_gsum[GROUPS];
__device__ unsigned int g_c1[GROUPS];               // zero-init; reset by finisher
__device__ unsigned int g_c2;                       // zero-init; reset by finisher

__device__ __forceinline__ int cidx(float v, float bmin, float inv) {
    int i = (int)((v - bmin) * inv);
    return min(max(i, 0), NC - 1);
}

// ---- one fused prep: bbox -> histogram -> scan -> scatter (per set,batch) ----
__global__ __launch_bounds__(PTH) void k_prep(const float* __restrict__ rec,
                                              const float* __restrict__ data) {
    __shared__ float          sbox[6][PTH];
    __shared__ int            hist[NCELLS];
    __shared__ unsigned short cells[NPTS];
    __shared__ int            ssum[PTH];

    const int s   = blockIdx.x >> 2;
    const int b   = blockIdx.x & 3;
    const int tid = threadIdx.x;
    const float* src = (s == 0 ? rec : data) + (size_t)b * NPTS * 3;

    float mn0 = 3.4e38f, mn1 = 3.4e38f, mn2 = 3.4e38f;
    float mx0 = -3.4e38f, mx1 = -3.4e38f, mx2 = -3.4e38f;
    for (int i = tid; i < NPTS; i += PTH) {
        float x = src[3 * i], y = src[3 * i + 1], z = src[3 * i + 2];
        mn0 = fminf(mn0, x); mx0 = fmaxf(mx0, x);
        mn1 = fminf(mn1, y); mx1 = fmaxf(mx1, y);
        mn2 = fminf(mn2, z); mx2 = fmaxf(mx2, z);
    }
    sbox[0][tid] = mn0; sbox[1][tid] = mn1; sbox[2][tid] = mn2;
    sbox[3][tid] = mx0; sbox[4][tid] = mx1; sbox[5][tid] = mx2;
    __syncthreads();
    for (int st = PTH / 2; st > 0; st >>= 1) {
        if (tid < st) {
            #pragma unroll
            for (int a = 0; a < 3; ++a) {
                sbox[a][tid]     = fminf(sbox[a][tid],     sbox[a][tid + st]);
                sbox[a + 3][tid] = fmaxf(sbox[a + 3][tid], sbox[a + 3][tid + st]);
            }
        }
        __syncthreads();
    }
    if (tid < 6) g_box[s][b][tid] = sbox[tid][0];
    const float bx0 = sbox[0][0], by0 = sbox[1][0], bz0 = sbox[2][0];
    const float ivx = NC / (sbox[3][0] - bx0 + 1e-6f);
    const float ivy = NC / (sbox[4][0] - by0 + 1e-6f);
    const float ivz = NC / (sbox[5][0] - bz0 + 1e-6f);
    __syncthreads();

    for (int i = tid; i < NCELLS; i += PTH) hist[i] = 0;
    __syncthreads();
    for (int i = tid; i < NPTS; i += PTH) {
        float x = src[3 * i], y = src[3 * i + 1], z = src[3 * i + 2];
        int c = (cidx(z, bz0, ivz) * NC + cidx(y, by0, ivy)) * NC + cidx(x, bx0, ivx);
        cells[i] = (unsigned short)c;
        atomicAdd(&hist[c], 1);
    }
    __syncthreads();

    const int base = tid * 8;
    int loc[8], tot = 0;
    #pragma unroll
    for (int j = 0; j < 8; ++j) { loc[j] = tot; tot += hist[base + j]; }
    ssum[tid] = tot;
    __syncthreads();
    for (int off = 1; off < PTH; off <<= 1) {
        int v = (tid >= off) ? ssum[tid - off] : 0;
        __syncthreads();
        ssum[tid] += v;
        __syncthreads();
    }
    const int ex = ssum[tid] - tot;
    #pragma unroll
    for (int j = 0; j < 8; ++j) g_start[s][b][base + j] = ex + loc[j];
    if (tid == PTH - 1) g_start[s][b][NCELLS] = NPTS;
    __syncthreads();
    #pragma unroll
    for (int j = 0; j < 8; ++j) hist[base + j] = ex + loc[j];   // cursors
    __syncthreads();

    for (int i = tid; i < NPTS; i += PTH) {
        int c = cells[i];
        int pos = atomicAdd(&hist[c], 1);
        float x = src[3 * i], y = src[3 * i + 1], z = src[3 * i + 2];
        g_sorted[s][b][pos] = make_float4(x, y, z, fmaf(x, x, fmaf(y, y, z * z)));
    }
}

// ---- exact NN: block stages union of 3x3x3 neighborhoods in SMEM ----
__global__ __launch_bounds__(STH) void k_search(float* __restrict__ out) {
    __shared__ float4 spts[CAP];                 // 32 KB staged points
    __shared__ int    rowgs[STH], rowoff[STH], rowlen[STH];
    __shared__ int    ssum[STH];
    __shared__ int    symin[NC], symax[NC];
    __shared__ int    s_czmin, s_czmax;
    __shared__ double red[STH];
    __shared__ int    s_flag;

    const int tid = threadIdx.x;
    const int dir = blockIdx.z;                  // 0: rec->data, 1: data->rec
    const int b   = blockIdx.y;
    const int qi  = blockIdx.x * STH + tid;
    const int ds  = 1 - dir;
    const int group = dir * NBATCH + b;

    const float4 q = g_sorted[dir][b][qi];
    const float* bx = g_box[ds][b];
    const float rx = bx[3] - bx[0] + 1e-6f;
    const float ry = bx[4] - bx[1] + 1e-6f;
    const float rz = bx[5] - bx[2] + 1e-6f;
    const float ivx = NC / rx, ivy = NC / ry, ivz = NC / rz;
    const float hmin = fminf(rx, fminf(ry, rz)) * (1.0f / NC);

    const float A0 = -2.0f * q.x, A1 = -2.0f * q.y, A2 = -2.0f * q.z;
    const float q2 = q.w;
    const int cx = cidx(q.x, bx[0], ivx);
    const int cy = cidx(q.y, bx[1], ivy);
    const int cz = cidx(q.z, bx[2], ivz);

    const float4* __restrict__ pts = g_sorted[ds][b];
    const int*    __restrict__ stt = g_start[ds][b];

    // ---- block query-cell extent ----
    if (tid < NC) { symin[tid] = 99; symax[tid] = -1; }
    if (tid == 0) { s_czmin = 99; s_czmax = -1; }
    __syncthreads();
    atomicMin(&symin[cz], cy);
    atomicMax(&symax[cz], cy);
    atomicMin(&s_czmin, cz);
    atomicMax(&s_czmax, cz);
    __syncthreads();

    const int zlo   = max(s_czmin - 1, 0);
    const int zhi   = min(s_czmax + 1, NC - 1);
    const int zspan = zhi - zlo + 1;

    // ---- per-row length (t = zi*NC + y), parallel ----
    int mylen = 0, mygs = 0;
    {
        const int zi = tid >> 4, y = tid & (NC - 1);
        const int z = zlo + zi;
        if (zspan <= ZSPAN && zi < zspan) {
            int yl = 99, yh = -1;
            #pragma unroll
            for (int dzq = -1; dzq <= 1; ++dzq) {
                int zq = z + dzq;
                if (zq >= 0 && zq < NC && symax[zq] >= 0) {
                    yl = min(yl, symin[zq]);
                    yh = max(yh, symax[zq]);
                }
            }
            if (yh >= 0) {
                int ylo2 = max(yl - 1, 0), yhi2 = min(yh + 1, NC - 1);
                if (y >= ylo2 && y <= yhi2) {
                    int rb = (z * NC + y) * NC;
                    mygs  = stt[rb];
                    mylen = stt[rb + NC] - mygs;
                }
            }
        }
    }
    ssum[tid] = mylen;
    __syncthreads();
    for (int off = 1; off < STH; off <<= 1) {
        int v = (tid >= off) ? ssum[tid - off] : 0;
        __syncthreads();
        ssum[tid] += v;
        __syncthreads();
    }
    rowgs[tid]  = mygs;
    rowoff[tid] = ssum[tid] - mylen;
    rowlen[tid] = mylen;
    __syncthreads();
    const bool fb = (zspan > ZSPAN) || (ssum[STH - 1] > CAP);  // block-uniform

    if (!fb) {
        // ---- stage rows (coalesced float4 copies) ----
        for (int r = 0; r < ZSPAN * NC; ++r) {
            const int len = rowlen[r];
            if (!len) continue;
            const int gsr = rowgs[r], offr = rowoff[r];
            for (int i = tid; i < len; i += STH)
                spts[offr + i] = pts[gsr + i];
        }
        __syncthreads();
    }

    // ---- fast path: 3x3x3 as 9 x-runs ----
    float b0 = 3.4e38f, b1 = 3.4e38f;
    const int xlo = max(cx - 1, 0), xhi = min(cx + 1, NC - 1);
    const int ylo1 = max(cy - 1, 0), yhi1 = min(cy + 1, NC - 1);
    const int zlo1 = max(cz - 1, 0), zhi1 = min(cz + 1, NC - 1);

    if (!fb) {
        for (int z = zlo1; z <= zhi1; ++z) {
            const int zi = z - zlo;
            for (int y = ylo1; y <= yhi1; ++y) {
                const int t = zi * NC + y;
                const int rb = (z * NC + y) * NC;
                const int adj = rowoff[t] - rowgs[t];
                int i = stt[rb + xlo] + adj;
                const int e = stt[rb + xhi + 1] + adj;
                for (; i + 1 < e; i += 2) {
                    float4 p  = spts[i];
                    float4 p2 = spts[i + 1];
                    b0 = fminf(b0, fmaf(A2, p.z,  fmaf(A1, p.y,  fmaf(A0, p.x,  q2))) + p.w);
                    b1 = fminf(b1, fmaf(A2, p2.z, fmaf(A1, p2.y, fmaf(A0, p2.x, q2))) + p2.w);
                }
                if (i < e) {
                    float4 p = spts[i];
                    b0 = fminf(b0, fmaf(A2, p.z, fmaf(A1, p.y, fmaf(A0, p.x, q2))) + p.w);
                }
            }
        }
    } else {
        for (int z = zlo1; z <= zhi1; ++z)
            for (int y = ylo1; y <= yhi1; ++y) {
                const int rb = (z * NC + y) * NC;
                int i = stt[rb + xlo];
                const int e = stt[rb + xhi + 1];
                for (; i + 1 < e; i += 2) {
                    float4 p  = pts[i];
                    float4 p2 = pts[i + 1];
                    b0 = fminf(b0, fmaf(A2, p.z,  fmaf(A1, p.y,  fmaf(A0, p.x,  q2))) + p.w);
                    b1 = fminf(b1, fmaf(A2, p2.z, fmaf(A1, p2.y, fmaf(A0, p2.x, q2))) + p2.w);
                }
                if (i < e) {
                    float4 p = pts[i];
                    b0 = fminf(b0, fmaf(A2, p.z, fmaf(A1, p.y, fmaf(A0, p.x, q2))) + p.w);
                }
            }
    }
    float best = fminf(b0, b1);

    // ---- rare path: incremental Chebyshev shells from global ----
    if (best > hmin * hmin) {
        for (int k = 2; k < NC; ++k) {
            const float lb = (k - 1) * hmin;
            if (best <= lb * lb) break;
            for (int dz = -k; dz <= k; ++dz) {
                const int z = cz + dz;
                if (z < 0 || z >= NC) continue;
                const int adz = (dz < 0) ? -dz : dz;
                for (int dy = -k; dy <= k; ++dy) {
                    const int y = cy + dy;
                    if (y < 0 || y >= NC) continue;
                    const int ady = (dy < 0) ? -dy : dy;
                    const int rb = (z * NC + y) * NC;
                    if (adz == k || ady == k) {
                        const int xl = max(cx - k, 0), xh = min(cx + k, NC - 1);
                        int i = stt[rb + xl];
                        const int e = stt[rb + xh + 1];
                        for (; i < e; ++i) {
                            float4 p = pts[i];
                            best = fminf(best,
                                fmaf(A2, p.z, fmaf(A1, p.y, fmaf(A0, p.x, q2))) + p.w);
                        }
                    } else {
                        const int xm = cx - k, xp = cx + k;
                        if (xm >= 0) {
                            int i = stt[rb + xm];
                            const int e = stt[rb + xm + 1];
                            for (; i < e; ++i) {
                                float4 p = pts[i];
                                best = fminf(best,
                                    fmaf(A2, p.z, fmaf(A1, p.y, fmaf(A0, p.x, q2))) + p.w);
                            }
                        }
                        if (xp < NC) {
                            int i = stt[rb + xp];
                            const int e = stt[rb + xp + 1];
                            for (; i < e; ++i) {
                                float4 p = pts[i];
                                best = fminf(best,
                                    fmaf(A2, p.z, fmaf(A1, p.y, fmaf(A0, p.x, q2))) + p.w);
                            }
                        }
                    }
                }
            }
        }
    }

    // ---- double-precision reduction (scatter-order independent) ----
    red[tid] = (double)fmaxf(best, 0.0f);
    __syncthreads();
    for (int st = STH / 2; st > 0; st >>= 1) {
        if (tid < st) red[tid] += red[tid + st];
        __syncthreads();
    }
    if (tid == 0) {
        g_part[group][blockIdx.x] = red[0];
        __threadfence();
        unsigned int t = atomicAdd(&g_c1[group], 1u);
        s_flag = (t == SBLK - 1) ? 1 : 0;
    }
    __syncthreads();

    if (s_flag && tid == 0) {
        __threadfence();
        double ssumd = 0.0;
        #pragma unroll
        for (int c = 0; c < SBLK; ++c) ssumd += g_part[group][c];
        g_gsum[group] = ssumd;
        __threadfence();
        unsigned int t2 = atomicAdd(&g_c2, 1u);
        if (t2 == GROUPS - 1) {
            __threadfence();
            double total = 0.0;
            #pragma unroll
            for (int bb = 0; bb < NBATCH; ++bb) {
                double mr = g_gsum[0 * NBATCH + bb] * (1.0 / NPTS);
                double md = g_gsum[1 * NBATCH + bb] * (1.0 / NPTS);
                total += (mr > md) ? mr : md;
            }
            out[0] = (float)(total * (1.0 / NBATCH));
            #pragma unroll
            for (int gg = 0; gg < GROUPS; ++gg) g_c1[gg] = 0u;
            g_c2 = 0u;
        }
    }
}

extern "C" void kernel_launch(void* const* d_in, const int* in_sizes, int n_in,
                              void* d_out, int out_size) {
    const float* rec  = (const float*)d_in[0];   // (B, N, 3) fp32
    const float* data = (const float*)d_in[1];   // (B, M, 3) fp32
    float* out = (float*)d_out;

    k_prep<<<8, PTH>>>(rec, data);
    dim3 sgrid(SBLK, NBATCH, 2);                 // 64 x 4 x 2 = 512 blocks
    k_search<<<sgrid, STH>>>(out);
}